// round 12
// baseline (speedup 1.0000x reference)
#include <cuda_runtime.h>
#include <cuda_bf16.h>
#include <cstdint>

// Problem: B=4, L=2048, H=8, D=64.
// Reference math collapses: out[b,q,h,d] = (sum_w softmax[.]) * (sum_e V[b,e,h,d])
//                                        = 1 * sum_l V[b,l,h,d]
// Q, K are dead inputs. Column-sum V over L, broadcast over q.
//
// R12: single launch, ONE grid barrier. Tree reduction replaced by
// deterministic fixed-point int64 RED.ADD (order-independent => bit-stable).
// Ping-pong accumulator indexed by generation parity removes the need to
// re-zero before accumulating (partner buffer is zeroed post-barrier, while
// nobody reads it; next launch flips parity).

#define B_DIM 4
#define L_DIM 2048
#define HD 512                  // floats per (b,l) row
#define HD4 128                 // float4 per row
#define NBLK 512
#define NTHR 256
#define ROWS 16                 // V rows per block (32 KB tile)
#define CHUNKS_PER_B 128        // 2048/16
#define TILE_BYTES (ROWS * HD * 4)     // 32768

// Fixed-point scale 2^36: |col_partial| <= ~16*6, sum of 128 partials fits
// int64 with huge headroom; quantization error ~2^-36 absolute.
#define ACC_SCALE  68719476736.0        // 2^36
#define ACC_INV    (1.0 / 68719476736.0)

// Scratch (allocation-free __device__ globals; zero-initialized at load)
__device__ long long g_acc[2][B_DIM * HD];   // 32 KB total, L2-resident
__device__ unsigned g_count = 0;
__device__ unsigned g_gen = 0;               // monotonic across replays

__device__ __forceinline__ float4 f4add(float4 a, float4 b) {
    a.x += b.x; a.y += b.y; a.z += b.z; a.w += b.w; return a;
}
__device__ __forceinline__ uint32_t smem_u32(const void* p) {
    return (uint32_t)__cvta_generic_to_shared(p);
}

__global__ void __launch_bounds__(NTHR) fused_kernel(const float* __restrict__ V,
                                                     float* __restrict__ out) {
    __shared__ alignas(128) float4 tile[ROWS * HD4];   // 32 KB, reused r/w
    __shared__ float4 sdata[NTHR];                     // 4 KB
    __shared__ alignas(8) uint64_t mbar;

    const int blk = blockIdx.x;
    const int t = threadIdx.x;
    const int c = t & 127;          // float4 column
    const int p = t >> 7;           // row-half 0/1
    const int b = blk >> 7;         // 128 chunks per batch
    const int chunk = blk & 127;

    // Generation parity: stable for the whole pre-barrier phase (g_gen only
    // increments at this launch's barrier release).
    const unsigned gen0 = atomicAdd(&g_gen, 0u);
    const unsigned par = gen0 & 1u;

    // ---------------- Phase 1: stream chunk + fold + RED.ADD ----------------
    {
        const uint32_t mb = smem_u32(&mbar);
        if (t == 0)
            asm volatile("mbarrier.init.shared.b64 [%0], 1;" :: "r"(mb) : "memory");
        __syncthreads();
        if (t == 0) {
            asm volatile("mbarrier.arrive.expect_tx.shared.b64 _, [%0], %1;"
                         :: "r"(mb), "r"((uint32_t)TILE_BYTES) : "memory");
            const float* src = V + ((size_t)(b * L_DIM + chunk * ROWS)) * HD;
            asm volatile(
                "cp.async.bulk.shared::cluster.global.mbarrier::complete_tx::bytes "
                "[%0], [%1], %2, [%3];"
                :: "r"(smem_u32(tile)), "l"(src), "r"((uint32_t)TILE_BYTES), "r"(mb)
                : "memory");
        }
        uint32_t done = 0;
        do {
            asm volatile(
                "{\n\t.reg .pred q;\n\t"
                "mbarrier.try_wait.parity.shared.b64 q, [%1], 0;\n\t"
                "selp.b32 %0, 1, 0, q;\n\t}"
                : "=r"(done) : "r"(mb) : "memory");
        } while (!done);

        // thread (p,c) sums 8 rows of column c; fold halves via smem
        float4 a0 = f4add(tile[(p * 8 + 0) * HD4 + c], tile[(p * 8 + 1) * HD4 + c]);
        float4 a1 = f4add(tile[(p * 8 + 2) * HD4 + c], tile[(p * 8 + 3) * HD4 + c]);
        float4 a2 = f4add(tile[(p * 8 + 4) * HD4 + c], tile[(p * 8 + 5) * HD4 + c]);
        float4 a3 = f4add(tile[(p * 8 + 6) * HD4 + c], tile[(p * 8 + 7) * HD4 + c]);
        sdata[t] = f4add(f4add(a0, a1), f4add(a2, a3));
        __syncthreads();
        if (t < 128) {
            float4 s = f4add(sdata[t], sdata[t + 128]);
            long long* acc = &g_acc[par][b * HD + t * 4];
            atomicAdd((unsigned long long*)&acc[0],
                      (unsigned long long)__double2ll_rn((double)s.x * ACC_SCALE));
            atomicAdd((unsigned long long*)&acc[1],
                      (unsigned long long)__double2ll_rn((double)s.y * ACC_SCALE));
            atomicAdd((unsigned long long*)&acc[2],
                      (unsigned long long)__double2ll_rn((double)s.z * ACC_SCALE));
            atomicAdd((unsigned long long*)&acc[3],
                      (unsigned long long)__double2ll_rn((double)s.w * ACC_SCALE));
        }
    }

    // ---------------- Single grid barrier ----------------
    __syncthreads();
    if (t == 0) {
        __threadfence();
        unsigned arv = atomicAdd(&g_count, 1u);
        if (arv == NBLK - 1u) {
            atomicExch(&g_count, 0u);
            __threadfence();
            atomicAdd(&g_gen, 1u);                  // release (flips parity)
        } else {
            while (atomicAdd(&g_gen, 0u) == gen0) { __nanosleep(64); }
        }
    }
    __syncthreads();

    // ---------------- Phase 2: zero partner buffer + broadcast write ----------
    {
        // Zero next launch's accumulator (nobody reads par^1 this launch;
        // next launch's atomics start only after this kernel fully exits).
        if (t < 4)
            g_acc[par ^ 1u][blk * 4 + t] = 0ll;

        // Read this batch's column sums (4 KB slice, L2-hot) and convert.
        const long long* acc = &g_acc[par][b * HD + c * 4];
        float4 v;
        v.x = (float)((double)acc[0] * ACC_INV);
        v.y = (float)((double)acc[1] * ACC_INV);
        v.z = (float)((double)acc[2] * ACC_INV);
        v.w = (float)((double)acc[3] * ACC_INV);

        // Replicate into 16 q-rows of the 32 KB tile (STS.128, conflict-free).
#pragma unroll
        for (int i = 0; i < 8; ++i)
            tile[(p * 8 + i) * HD4 + c] = v;
        __syncthreads();

        if (t == 0) {
            asm volatile("fence.proxy.async;" ::: "memory");
            float* dst = out + ((size_t)(b * L_DIM + chunk * ROWS)) * HD;
            asm volatile(
                "cp.async.bulk.global.shared::cta.bulk_group [%0], [%1], %2;"
                :: "l"(dst), "r"(smem_u32(tile)), "r"((uint32_t)TILE_BYTES)
                : "memory");
            asm volatile("cp.async.bulk.commit_group;" ::: "memory");
            asm volatile("cp.async.bulk.wait_group 0;" ::: "memory");
        }
    }
}

extern "C" void kernel_launch(void* const* d_in, const int* in_sizes, int n_in,
                              void* d_out, int out_size) {
    // inputs: [0] queries, [1] keys, [2] values (float32). Q, K unused by the math.
    const float* V = (const float*)d_in[2];
    float* out = (float*)d_out;
    fused_kernel<<<NBLK, NTHR>>>(V, out);
}

// round 14
// speedup vs baseline: 5.0186x; 5.0186x over previous
#include <cuda_runtime.h>
#include <cuda_bf16.h>
#include <cstdint>

// Problem: B=4, L=2048, H=8, D=64.
// Reference math collapses: out[b,q,h,d] = (sum_w softmax[.]) * (sum_e V[b,e,h,d])
//                                        = 1 * sum_l V[b,l,h,d]
// Q, K dead inputs. Column-sum V over L, broadcast over q.
//
// R13 = R12 with atomic discipline fixed. R12's 103us came from ONE line:
// per-thread atomicAdd(&g_gen,0) = 131072 serialized same-address atomics
// (~75us). Fixes: (1) gen read = plain ld.cg by thread 0 + smem broadcast;
// (2) accumulation uses no-return atomics (REDG) on 2048 spread addresses;
// (3) barrier spin polls with ld.cg, not atomics. Structure (single launch,
// one grid barrier, int64 fixed-point determinism, parity ping-pong) kept.

#define B_DIM 4
#define L_DIM 2048
#define HD 512                  // floats per (b,l) row
#define HD4 128                 // float4 per row
#define NBLK 512
#define NTHR 256
#define ROWS 16                 // V rows per block (32 KB tile)
#define TILE_BYTES (ROWS * HD * 4)     // 32768

#define ACC_SCALE  68719476736.0        // 2^36
#define ACC_INV    (1.0 / 68719476736.0)

// Scratch (allocation-free __device__ globals; zero-initialized at load)
__device__ long long g_acc[2][B_DIM * HD];   // 32 KB, L2-resident
__device__ unsigned g_count = 0;
__device__ volatile unsigned g_gen = 0;      // monotonic across replays

__device__ __forceinline__ float4 f4add(float4 a, float4 b) {
    a.x += b.x; a.y += b.y; a.z += b.z; a.w += b.w; return a;
}
__device__ __forceinline__ uint32_t smem_u32(const void* p) {
    return (uint32_t)__cvta_generic_to_shared(p);
}
__device__ __forceinline__ unsigned ld_cg_u32(const volatile unsigned* p) {
    unsigned v;
    asm volatile("ld.global.cg.u32 %0, [%1];" : "=r"(v) : "l"((const unsigned*)p));
    return v;
}
__device__ __forceinline__ void red_add_ll(long long* p, long long v) {
    asm volatile("red.global.add.u64 [%0], %1;" :: "l"(p), "l"(v) : "memory");
}

__global__ void __launch_bounds__(NTHR) fused_kernel(const float* __restrict__ V,
                                                     float* __restrict__ out) {
    __shared__ alignas(128) float4 tile[ROWS * HD4];   // 32 KB, reused r/w
    __shared__ float4 sdata[NTHR];                     // 4 KB
    __shared__ alignas(8) uint64_t mbar;
    __shared__ unsigned s_gen;

    const int blk = blockIdx.x;
    const int t = threadIdx.x;
    const int c = t & 127;          // float4 column
    const int p = t >> 7;           // row-half 0/1
    const int b = blk >> 7;         // 128 chunks per batch
    const int chunk = blk & 127;

    // ---------------- Phase 1: TMA chunk + fold + REDG ----------------
    const uint32_t mb = smem_u32(&mbar);
    if (t == 0) {
        s_gen = ld_cg_u32(&g_gen);   // single read per block, no atomic
        asm volatile("mbarrier.init.shared.b64 [%0], 1;" :: "r"(mb) : "memory");
    }
    __syncthreads();
    const unsigned gen0 = s_gen;
    const unsigned par = gen0 & 1u;

    if (t == 0) {
        asm volatile("mbarrier.arrive.expect_tx.shared.b64 _, [%0], %1;"
                     :: "r"(mb), "r"((uint32_t)TILE_BYTES) : "memory");
        const float* src = V + ((size_t)(b * L_DIM + chunk * ROWS)) * HD;
        asm volatile(
            "cp.async.bulk.shared::cluster.global.mbarrier::complete_tx::bytes "
            "[%0], [%1], %2, [%3];"
            :: "r"(smem_u32(tile)), "l"(src), "r"((uint32_t)TILE_BYTES), "r"(mb)
            : "memory");
    }
    {
        uint32_t done = 0;
        do {
            asm volatile(
                "{\n\t.reg .pred q;\n\t"
                "mbarrier.try_wait.parity.shared.b64 q, [%1], 0;\n\t"
                "selp.b32 %0, 1, 0, q;\n\t}"
                : "=r"(done) : "r"(mb) : "memory");
        } while (!done);
    }

    // thread (p,c) sums 8 rows of column c; fold halves via smem
    {
        float4 a0 = f4add(tile[(p * 8 + 0) * HD4 + c], tile[(p * 8 + 1) * HD4 + c]);
        float4 a1 = f4add(tile[(p * 8 + 2) * HD4 + c], tile[(p * 8 + 3) * HD4 + c]);
        float4 a2 = f4add(tile[(p * 8 + 4) * HD4 + c], tile[(p * 8 + 5) * HD4 + c]);
        float4 a3 = f4add(tile[(p * 8 + 6) * HD4 + c], tile[(p * 8 + 7) * HD4 + c]);
        sdata[t] = f4add(f4add(a0, a1), f4add(a2, a3));
    }
    __syncthreads();
    if (t < 128) {
        float4 s = f4add(sdata[t], sdata[t + 128]);
        long long* acc = &g_acc[par][b * HD + t * 4];
        red_add_ll(&acc[0], __double2ll_rn((double)s.x * ACC_SCALE));
        red_add_ll(&acc[1], __double2ll_rn((double)s.y * ACC_SCALE));
        red_add_ll(&acc[2], __double2ll_rn((double)s.z * ACC_SCALE));
        red_add_ll(&acc[3], __double2ll_rn((double)s.w * ACC_SCALE));
    }

    // ---------------- Single grid barrier (leaders only) ----------------
    __syncthreads();
    if (t == 0) {
        __threadfence();
        unsigned arv = atomicAdd(&g_count, 1u);     // only atomic-with-return
        if (arv == NBLK - 1u) {
            g_count = 0;                            // plain store, pre-release
            __threadfence();
            atomicAdd((unsigned*)&g_gen, 1u);       // release (flips parity)
        } else {
            while (ld_cg_u32(&g_gen) == gen0) { __nanosleep(128); }
        }
    }
    __syncthreads();

    // ---------------- Phase 2: zero partner + broadcast write ----------------
    // Zero next launch's accumulator (nobody touches par^1 this launch).
    if (t < 4)
        g_acc[par ^ 1u][blk * 4 + t] = 0ll;

    // Read this batch's column sums (4 KB slice, L2-hot) and convert.
    {
        const long long* acc = &g_acc[par][b * HD + c * 4];
        float4 v;
        v.x = (float)((double)acc[0] * ACC_INV);
        v.y = (float)((double)acc[1] * ACC_INV);
        v.z = (float)((double)acc[2] * ACC_INV);
        v.w = (float)((double)acc[3] * ACC_INV);

        // Replicate into 16 q-rows of the 32 KB tile (STS.128, conflict-free).
#pragma unroll
        for (int i = 0; i < 8; ++i)
            tile[(p * 8 + i) * HD4 + c] = v;
    }
    __syncthreads();

    if (t == 0) {
        asm volatile("fence.proxy.async;" ::: "memory");
        float* dst = out + ((size_t)(b * L_DIM + chunk * ROWS)) * HD;
        asm volatile(
            "cp.async.bulk.global.shared::cta.bulk_group [%0], [%1], %2;"
            :: "l"(dst), "r"(smem_u32(tile)), "r"((uint32_t)TILE_BYTES)
            : "memory");
        asm volatile("cp.async.bulk.commit_group;" ::: "memory");
        asm volatile("cp.async.bulk.wait_group 0;" ::: "memory");
    }
}

extern "C" void kernel_launch(void* const* d_in, const int* in_sizes, int n_in,
                              void* d_out, int out_size) {
    // inputs: [0] queries, [1] keys, [2] values (float32). Q, K unused by the math.
    const float* V = (const float*)d_in[2];
    float* out = (float*)d_out;
    fused_kernel<<<NBLK, NTHR>>>(V, out);
}